// round 11
// baseline (speedup 1.0000x reference)
#include <cuda_runtime.h>
#include <cstdint>

// KoopmanOperator: y_{t+1} = R(p(y_t)), 256 steps, y_0 = x[:,0,:]
//   h = tanh(y @ W1^T + b1);  p = h @ W2^T + b2
//   mu=p[2i], om=p[2i+1]; e=exp(dt*mu), c=cos(dt*om), s=sin(dt*om)
//   y'[2i] = e*(c*y0 - s*y1);  y'[2i+1] = e*(s*y0 - c*y1)   (per reference)
//
// Register-resident weights: thread owns column j; W1[j][:], W2[j][:] live in
// 64 packed f32x2 registers. Inner loops read ONLY Y/H from smem, and every
// LDS.128 is warp-uniform (broadcast, conflict-free). 128 CTAs x 32 rows,
// 256 threads = 4 independent 64-thread groups (8 rows each) synced by named
// barriers; groups interleave across SMSPs for latency hiding.

#define D 64
#define T_STEPS 256
#define ROWS_PER_CTA 32
#define THREADS 256
#define NCTA 128
#define STRIDE 68               // floats; 272B pitch keeps rows bank-shifted
#define DT 0.01f

__device__ __forceinline__ void fma2(unsigned long long& d,
                                     unsigned long long a,
                                     unsigned long long b) {
    asm("fma.rn.f32x2 %0, %1, %2, %0;" : "+l"(d) : "l"(a), "l"(b));
}
__device__ __forceinline__ unsigned long long pack2(float x, float y) {
    unsigned long long u;
    asm("mov.b64 %0, {%1, %2};" : "=l"(u) : "f"(x), "f"(y));
    return u;
}
__device__ __forceinline__ float2 unpack2(unsigned long long u) {
    float2 f;
    asm("mov.b64 {%0, %1}, %2;" : "=f"(f.x), "=f"(f.y) : "l"(u));
    return f;
}

// Accurate fast tanh (~1e-6): EX2 + RCP.
__device__ __forceinline__ float tanh_acc(float x) {
    float ax = fabsf(x);
    float e  = __expf(-2.0f * ax);
    float t  = __fdividef(1.0f - e, 1.0f + e);
    return copysignf(t, x);
}
// Small-argument Taylor (|z| <~ 0.3): error < 1e-7, pure FFMA.
__device__ __forceinline__ float exp_small(float z) {
    float p = fmaf(z, 1.0f / 120.0f, 1.0f / 24.0f);
    p = fmaf(z, p, 1.0f / 6.0f);
    p = fmaf(z, p, 0.5f);
    p = fmaf(z, p, 1.0f);
    return fmaf(z, p, 1.0f);
}
__device__ __forceinline__ float cos_small(float z2) {
    float p = fmaf(z2, -1.0f / 720.0f, 1.0f / 24.0f);
    p = fmaf(z2, p, -0.5f);
    return fmaf(z2, p, 1.0f);
}
__device__ __forceinline__ float sin_small(float z, float z2) {
    float p = fmaf(z2, 1.0f / 120.0f, -1.0f / 6.0f);
    return z * fmaf(z2, p, 1.0f);
}

// 8-row GEMV with register-resident weight column wp[32] (f32x2 k-pairs).
// src rows are warp-uniform broadcast loads. Writes out8[0..7] (pre-activation).
__device__ __forceinline__ void gemv_regw(const unsigned long long* __restrict__ wp,
                                          const float* __restrict__ src,
                                          int r0, float bias, float out8[8]) {
#pragma unroll
    for (int rb = 0; rb < 8; rb += 4) {
        unsigned long long acc[4];
#pragma unroll
        for (int i = 0; i < 4; i++) acc[i] = pack2(bias, 0.0f);
#pragma unroll
        for (int kc = 0; kc < D; kc += 4) {
            ulonglong2 yv[4];
#pragma unroll
            for (int i = 0; i < 4; i++)
                yv[i] = *reinterpret_cast<const ulonglong2*>(
                    src + (r0 + rb + i) * STRIDE + kc);
            const unsigned long long wlo = wp[kc >> 1];
            const unsigned long long whi = wp[(kc >> 1) + 1];
#pragma unroll
            for (int i = 0; i < 4; i++) fma2(acc[i], wlo, yv[i].x);
#pragma unroll
            for (int i = 0; i < 4; i++) fma2(acc[i], whi, yv[i].y);
        }
#pragma unroll
        for (int i = 0; i < 4; i++) {
            float2 v = unpack2(acc[i]);
            out8[rb + i] = v.x + v.y;
        }
    }
}

__global__ void __launch_bounds__(THREADS, 1)
koopman_kernel(const float* __restrict__ x,
               const float* __restrict__ W1g,
               const float* __restrict__ b1g,
               const float* __restrict__ W2g,
               const float* __restrict__ b2g,
               float* __restrict__ out) {
    __shared__ float Ys[ROWS_PER_CTA * STRIDE];
    __shared__ float Hs[ROWS_PER_CTA * STRIDE];

    const int tid  = threadIdx.x;
    const int w    = tid >> 5;
    const int lane = tid & 31;
    const int g    = w >> 1;            // group 0..3 -> rows [8g, 8g+8)
    const int half = w & 1;             // col half
    const int j    = 32 * half + lane;  // owned column 0..63
    const int r0   = 8 * g;
    const int bar  = 1 + g;
    const int rowbase = blockIdx.x * ROWS_PER_CTA;

    // ---- one-time: weights into registers (packed k-pairs), y0 into smem ----
    unsigned long long w1p[32], w2p[32];
#pragma unroll
    for (int kc = 0; kc < D; kc += 4) {
        float4 a = *reinterpret_cast<const float4*>(W1g + j * D + kc);
        float4 b = *reinterpret_cast<const float4*>(W2g + j * D + kc);
        w1p[kc >> 1]       = pack2(a.x, a.y);
        w1p[(kc >> 1) + 1] = pack2(a.z, a.w);
        w2p[kc >> 1]       = pack2(b.x, b.y);
        w2p[(kc >> 1) + 1] = pack2(b.z, b.w);
    }
    const float b1j = b1g[j];
    const float b2j = b2g[j];

    for (int i = tid; i < ROWS_PER_CTA * D; i += THREADS) {
        int r = i >> 6, k = i & 63;
        Ys[r * STRIDE + k] = x[(size_t)(rowbase + r) * (T_STEPS * D) + k];
    }
    __syncthreads();

    const bool even = (lane & 1) == 0;

    for (int t = 0; t < T_STEPS; t++) {
        // ---- GEMV1 + tanh -> Hs (group-local rows) ----
        float hv[8];
        gemv_regw(w1p, Ys, r0, b1j, hv);
#pragma unroll
        for (int r = 0; r < 8; r++)
            Hs[(r0 + r) * STRIDE + j] = tanh_acc(hv[r]);
        asm volatile("bar.sync %0, 64;" :: "r"(bar) : "memory");

        // ---- GEMV2 -> p, fused rotation update via lane-pair shuffles ----
        float pv[8];
        gemv_regw(w2p, Hs, r0, b2j, pv);
#pragma unroll
        for (int r = 0; r < 8; r++) {
            const int rr = r0 + r;
            float p_m = pv[r];
            float p_o = __shfl_xor_sync(0xffffffffu, p_m, 1);
            float y_m = Ys[rr * STRIDE + j];
            float y_o = __shfl_xor_sync(0xffffffffu, y_m, 1);
            float mu = even ? p_m : p_o;
            float om = even ? p_o : p_m;
            float y0 = even ? y_m : y_o;
            float y1 = even ? y_o : y_m;
            float e  = exp_small(DT * mu);
            float z  = DT * om, z2 = z * z;
            float c  = cos_small(z2);
            float s  = sin_small(z, z2);
            float n  = even ? e * (c * y0 - s * y1)
                            : e * (s * y0 - c * y1);   // reference: s*y0 - c*y1
            Ys[rr * STRIDE + j] = n;
            out[((size_t)(rowbase + rr) * T_STEPS + t) * D + j] = n;
        }
        asm volatile("bar.sync %0, 64;" :: "r"(bar) : "memory");
    }
}

extern "C" void kernel_launch(void* const* d_in, const int* in_sizes, int n_in,
                              void* d_out, int out_size) {
    const float* x  = (const float*)d_in[0];
    const float* W1 = (const float*)d_in[1];
    const float* b1 = (const float*)d_in[2];
    const float* W2 = (const float*)d_in[3];
    const float* b2 = (const float*)d_in[4];
    float* out = (float*)d_out;

    // 4096 rows / 32 per CTA = 128 CTAs; static smem (~17 KB); weights in regs.
    koopman_kernel<<<NCTA, THREADS>>>(x, W1, b1, W2, b2, out);
}

// round 12
// speedup vs baseline: 1.0003x; 1.0003x over previous
#include <cuda_runtime.h>
#include <cstdint>

// KoopmanOperator: y_{t+1} = R(p(y_t)), 256 steps, y_0 = x[:,0,:]
//   h = tanh(y @ W1^T + b1);  p = h @ W2^T + b2
//   mu=p[2i], om=p[2i+1]; e=exp(dt*mu), c=cos(dt*om), s=sin(dt*om)
//   y'[2i] = e*(c*y0 - s*y1);  y'[2i+1] = e*(s*y0 - c*y1)   (per reference)
//
// Register-resident weights: thread owns column j; W1[j][:], W2[j][:] live in
// 64 packed f32x2 registers. Inner loops read ONLY Y/H from smem, and every
// LDS.128 is warp-uniform (broadcast, conflict-free). 128 CTAs x 32 rows,
// 256 threads = 4 independent 64-thread groups (8 rows each) synced by named
// barriers; groups interleave across SMSPs for latency hiding.

#define D 64
#define T_STEPS 256
#define ROWS_PER_CTA 32
#define THREADS 256
#define NCTA 128
#define STRIDE 68               // floats; 272B pitch keeps rows bank-shifted
#define DT 0.01f

__device__ __forceinline__ void fma2(unsigned long long& d,
                                     unsigned long long a,
                                     unsigned long long b) {
    asm("fma.rn.f32x2 %0, %1, %2, %0;" : "+l"(d) : "l"(a), "l"(b));
}
__device__ __forceinline__ unsigned long long pack2(float x, float y) {
    unsigned long long u;
    asm("mov.b64 %0, {%1, %2};" : "=l"(u) : "f"(x), "f"(y));
    return u;
}
__device__ __forceinline__ float2 unpack2(unsigned long long u) {
    float2 f;
    asm("mov.b64 {%0, %1}, %2;" : "=f"(f.x), "=f"(f.y) : "l"(u));
    return f;
}

// Accurate fast tanh (~1e-6): EX2 + RCP.
__device__ __forceinline__ float tanh_acc(float x) {
    float ax = fabsf(x);
    float e  = __expf(-2.0f * ax);
    float t  = __fdividef(1.0f - e, 1.0f + e);
    return copysignf(t, x);
}
// Small-argument Taylor (|z| <~ 0.3): error < 1e-7, pure FFMA.
__device__ __forceinline__ float exp_small(float z) {
    float p = fmaf(z, 1.0f / 120.0f, 1.0f / 24.0f);
    p = fmaf(z, p, 1.0f / 6.0f);
    p = fmaf(z, p, 0.5f);
    p = fmaf(z, p, 1.0f);
    return fmaf(z, p, 1.0f);
}
__device__ __forceinline__ float cos_small(float z2) {
    float p = fmaf(z2, -1.0f / 720.0f, 1.0f / 24.0f);
    p = fmaf(z2, p, -0.5f);
    return fmaf(z2, p, 1.0f);
}
__device__ __forceinline__ float sin_small(float z, float z2) {
    float p = fmaf(z2, 1.0f / 120.0f, -1.0f / 6.0f);
    return z * fmaf(z2, p, 1.0f);
}

// 8-row GEMV with register-resident weight column wp[32] (f32x2 k-pairs).
// src rows are warp-uniform broadcast loads. Writes out8[0..7] (pre-activation).
__device__ __forceinline__ void gemv_regw(const unsigned long long* __restrict__ wp,
                                          const float* __restrict__ src,
                                          int r0, float bias, float out8[8]) {
#pragma unroll
    for (int rb = 0; rb < 8; rb += 4) {
        unsigned long long acc[4];
#pragma unroll
        for (int i = 0; i < 4; i++) acc[i] = pack2(bias, 0.0f);
#pragma unroll
        for (int kc = 0; kc < D; kc += 4) {
            ulonglong2 yv[4];
#pragma unroll
            for (int i = 0; i < 4; i++)
                yv[i] = *reinterpret_cast<const ulonglong2*>(
                    src + (r0 + rb + i) * STRIDE + kc);
            const unsigned long long wlo = wp[kc >> 1];
            const unsigned long long whi = wp[(kc >> 1) + 1];
#pragma unroll
            for (int i = 0; i < 4; i++) fma2(acc[i], wlo, yv[i].x);
#pragma unroll
            for (int i = 0; i < 4; i++) fma2(acc[i], whi, yv[i].y);
        }
#pragma unroll
        for (int i = 0; i < 4; i++) {
            float2 v = unpack2(acc[i]);
            out8[rb + i] = v.x + v.y;
        }
    }
}

__global__ void __launch_bounds__(THREADS, 1)
koopman_kernel(const float* __restrict__ x,
               const float* __restrict__ W1g,
               const float* __restrict__ b1g,
               const float* __restrict__ W2g,
               const float* __restrict__ b2g,
               float* __restrict__ out) {
    __shared__ float Ys[ROWS_PER_CTA * STRIDE];
    __shared__ float Hs[ROWS_PER_CTA * STRIDE];

    const int tid  = threadIdx.x;
    const int w    = tid >> 5;
    const int lane = tid & 31;
    const int g    = w >> 1;            // group 0..3 -> rows [8g, 8g+8)
    const int half = w & 1;             // col half
    const int j    = 32 * half + lane;  // owned column 0..63
    const int r0   = 8 * g;
    const int bar  = 1 + g;
    const int rowbase = blockIdx.x * ROWS_PER_CTA;

    // ---- one-time: weights into registers (packed k-pairs), y0 into smem ----
    unsigned long long w1p[32], w2p[32];
#pragma unroll
    for (int kc = 0; kc < D; kc += 4) {
        float4 a = *reinterpret_cast<const float4*>(W1g + j * D + kc);
        float4 b = *reinterpret_cast<const float4*>(W2g + j * D + kc);
        w1p[kc >> 1]       = pack2(a.x, a.y);
        w1p[(kc >> 1) + 1] = pack2(a.z, a.w);
        w2p[kc >> 1]       = pack2(b.x, b.y);
        w2p[(kc >> 1) + 1] = pack2(b.z, b.w);
    }
    const float b1j = b1g[j];
    const float b2j = b2g[j];

    for (int i = tid; i < ROWS_PER_CTA * D; i += THREADS) {
        int r = i >> 6, k = i & 63;
        Ys[r * STRIDE + k] = x[(size_t)(rowbase + r) * (T_STEPS * D) + k];
    }
    __syncthreads();

    const bool even = (lane & 1) == 0;

    for (int t = 0; t < T_STEPS; t++) {
        // ---- GEMV1 + tanh -> Hs (group-local rows) ----
        float hv[8];
        gemv_regw(w1p, Ys, r0, b1j, hv);
#pragma unroll
        for (int r = 0; r < 8; r++)
            Hs[(r0 + r) * STRIDE + j] = tanh_acc(hv[r]);
        asm volatile("bar.sync %0, 64;" :: "r"(bar) : "memory");

        // ---- GEMV2 -> p, fused rotation update via lane-pair shuffles ----
        float pv[8];
        gemv_regw(w2p, Hs, r0, b2j, pv);
#pragma unroll
        for (int r = 0; r < 8; r++) {
            const int rr = r0 + r;
            float p_m = pv[r];
            float p_o = __shfl_xor_sync(0xffffffffu, p_m, 1);
            float y_m = Ys[rr * STRIDE + j];
            float y_o = __shfl_xor_sync(0xffffffffu, y_m, 1);
            float mu = even ? p_m : p_o;
            float om = even ? p_o : p_m;
            float y0 = even ? y_m : y_o;
            float y1 = even ? y_o : y_m;
            float e  = exp_small(DT * mu);
            float z  = DT * om, z2 = z * z;
            float c  = cos_small(z2);
            float s  = sin_small(z, z2);
            float n  = even ? e * (c * y0 - s * y1)
                            : e * (s * y0 - c * y1);   // reference: s*y0 - c*y1
            Ys[rr * STRIDE + j] = n;
            out[((size_t)(rowbase + rr) * T_STEPS + t) * D + j] = n;
        }
        asm volatile("bar.sync %0, 64;" :: "r"(bar) : "memory");
    }
}

extern "C" void kernel_launch(void* const* d_in, const int* in_sizes, int n_in,
                              void* d_out, int out_size) {
    const float* x  = (const float*)d_in[0];
    const float* W1 = (const float*)d_in[1];
    const float* b1 = (const float*)d_in[2];
    const float* W2 = (const float*)d_in[3];
    const float* b2 = (const float*)d_in[4];
    float* out = (float*)d_out;

    // 4096 rows / 32 per CTA = 128 CTAs; static smem (~17 KB); weights in regs.
    koopman_kernel<<<NCTA, THREADS>>>(x, W1, b1, W2, b2, out);
}

// round 13
// speedup vs baseline: 1.0033x; 1.0031x over previous
#include <cuda_runtime.h>
#include <cstdint>

// KoopmanOperator: y_{t+1} = R(p(y_t)), 256 steps, y_0 = x[:,0,:]
//   h = tanh(y @ W1^T + b1);  p = h @ W2^T + b2
//   mu=p[2i], om=p[2i+1]; e=exp(dt*mu), c=cos(dt*om), s=sin(dt*om)
//   y'[2i] = e*(c*y0 - s*y1);  y'[2i+1] = e*(s*y0 - c*y1)   (per reference)
//
// Double-cohort pipeline: each 64-thread group owns 8 rows, split into
// cohorts A (4 rows) and B (4 rows), B half a step behind A. Every phase runs
// two INDEPENDENT GEMVs (one per cohort) fused instruction-level in
// dual_gemv4 (8 LDS.128 in flight, then 16 FFMA2) -> 2x the per-warp MLP of
// R11 with identical LDS/FFMA/barrier counts. Weights register-resident
// (thread owns column j of W1 and W2); all smem loads warp-uniform broadcast.

#define D 64
#define T_STEPS 256
#define ROWS_PER_CTA 32
#define THREADS 256
#define NCTA 128
#define STRIDE 68               // floats; 272B pitch
#define DT 0.01f

__device__ __forceinline__ void fma2(unsigned long long& d,
                                     unsigned long long a,
                                     unsigned long long b) {
    asm("fma.rn.f32x2 %0, %1, %2, %0;" : "+l"(d) : "l"(a), "l"(b));
}
__device__ __forceinline__ unsigned long long pack2(float x, float y) {
    unsigned long long u;
    asm("mov.b64 %0, {%1, %2};" : "=l"(u) : "f"(x), "f"(y));
    return u;
}
__device__ __forceinline__ float2 unpack2(unsigned long long u) {
    float2 f;
    asm("mov.b64 {%0, %1}, %2;" : "=f"(f.x), "=f"(f.y) : "l"(u));
    return f;
}

// Accurate fast tanh (~1e-6): EX2 + RCP.
__device__ __forceinline__ float tanh_acc(float x) {
    float ax = fabsf(x);
    float e  = __expf(-2.0f * ax);
    float t  = __fdividef(1.0f - e, 1.0f + e);
    return copysignf(t, x);
}
// Small-argument Taylor (|z| <~ 0.3): error < 1e-7, pure FFMA.
__device__ __forceinline__ float exp_small(float z) {
    float p = fmaf(z, 1.0f / 120.0f, 1.0f / 24.0f);
    p = fmaf(z, p, 1.0f / 6.0f);
    p = fmaf(z, p, 0.5f);
    p = fmaf(z, p, 1.0f);
    return fmaf(z, p, 1.0f);
}
__device__ __forceinline__ float cos_small(float z2) {
    float p = fmaf(z2, -1.0f / 720.0f, 1.0f / 24.0f);
    p = fmaf(z2, p, -0.5f);
    return fmaf(z2, p, 1.0f);
}
__device__ __forceinline__ float sin_small(float z, float z2) {
    float p = fmaf(z2, 1.0f / 120.0f, -1.0f / 6.0f);
    return z * fmaf(z2, p, 1.0f);
}

// Single 4-row GEMV, register weights (f32x2 k-pairs), broadcast src loads.
__device__ __forceinline__ void gemv4(const unsigned long long (&wp)[32],
                                      const float* __restrict__ src,
                                      int r0, float bias, float o[4]) {
    unsigned long long acc[4];
#pragma unroll
    for (int i = 0; i < 4; i++) acc[i] = pack2(bias, 0.0f);
#pragma unroll
    for (int kc = 0; kc < D; kc += 4) {
        ulonglong2 v[4];
#pragma unroll
        for (int i = 0; i < 4; i++)
            v[i] = *reinterpret_cast<const ulonglong2*>(src + (r0 + i) * STRIDE + kc);
        const unsigned long long lo = wp[kc >> 1], hi = wp[(kc >> 1) + 1];
#pragma unroll
        for (int i = 0; i < 4; i++) fma2(acc[i], lo, v[i].x);
#pragma unroll
        for (int i = 0; i < 4; i++) fma2(acc[i], hi, v[i].y);
    }
#pragma unroll
    for (int i = 0; i < 4; i++) {
        float2 f = unpack2(acc[i]);
        o[i] = f.x + f.y;
    }
}

// Two INDEPENDENT 4-row GEMVs, interleaved for MLP=8.
__device__ __forceinline__ void dual_gemv4(const unsigned long long (&wX)[32],
                                           const float* __restrict__ srcX,
                                           int rX, float bX,
                                           const unsigned long long (&wY)[32],
                                           const float* __restrict__ srcY,
                                           int rY, float bY,
                                           float oX[4], float oY[4]) {
    unsigned long long aX[4], aY[4];
#pragma unroll
    for (int i = 0; i < 4; i++) {
        aX[i] = pack2(bX, 0.0f);
        aY[i] = pack2(bY, 0.0f);
    }
#pragma unroll
    for (int kc = 0; kc < D; kc += 4) {
        ulonglong2 vx[4], vy[4];
#pragma unroll
        for (int i = 0; i < 4; i++)
            vx[i] = *reinterpret_cast<const ulonglong2*>(srcX + (rX + i) * STRIDE + kc);
#pragma unroll
        for (int i = 0; i < 4; i++)
            vy[i] = *reinterpret_cast<const ulonglong2*>(srcY + (rY + i) * STRIDE + kc);
        const unsigned long long xlo = wX[kc >> 1], xhi = wX[(kc >> 1) + 1];
        const unsigned long long ylo = wY[kc >> 1], yhi = wY[(kc >> 1) + 1];
#pragma unroll
        for (int i = 0; i < 4; i++) {
            fma2(aX[i], xlo, vx[i].x);
            fma2(aY[i], ylo, vy[i].x);
        }
#pragma unroll
        for (int i = 0; i < 4; i++) {
            fma2(aX[i], xhi, vx[i].y);
            fma2(aY[i], yhi, vy[i].y);
        }
    }
#pragma unroll
    for (int i = 0; i < 4; i++) {
        float2 fx = unpack2(aX[i]);
        float2 fy = unpack2(aY[i]);
        oX[i] = fx.x + fx.y;
        oY[i] = fy.x + fy.y;
    }
}

__global__ void __launch_bounds__(THREADS, 1)
koopman_kernel(const float* __restrict__ x,
               const float* __restrict__ W1g,
               const float* __restrict__ b1g,
               const float* __restrict__ W2g,
               const float* __restrict__ b2g,
               float* __restrict__ out) {
    __shared__ float Ys[ROWS_PER_CTA * STRIDE];
    __shared__ float Hs[ROWS_PER_CTA * STRIDE];

    const int tid  = threadIdx.x;
    const int w    = tid >> 5;
    const int lane = tid & 31;
    const int g    = w >> 1;            // group 0..3 -> rows [8g, 8g+8)
    const int half = w & 1;
    const int j    = 32 * half + lane;  // owned column
    const int rA   = 8 * g;             // cohort A rows
    const int rB   = 8 * g + 4;         // cohort B rows
    const int bar  = 1 + g;
    const int rowbase = blockIdx.x * ROWS_PER_CTA;
    const bool even = (lane & 1) == 0;

    // ---- weights into registers (packed k-pairs) ----
    unsigned long long w1p[32], w2p[32];
#pragma unroll
    for (int kc = 0; kc < D; kc += 4) {
        float4 a = *reinterpret_cast<const float4*>(W1g + j * D + kc);
        float4 b = *reinterpret_cast<const float4*>(W2g + j * D + kc);
        w1p[kc >> 1]       = pack2(a.x, a.y);
        w1p[(kc >> 1) + 1] = pack2(a.z, a.w);
        w2p[kc >> 1]       = pack2(b.x, b.y);
        w2p[(kc >> 1) + 1] = pack2(b.z, b.w);
    }
    const float b1j = b1g[j];
    const float b2j = b2g[j];

    for (int i = tid; i < ROWS_PER_CTA * D; i += THREADS) {
        int r = i >> 6, k = i & 63;
        Ys[r * STRIDE + k] = x[(size_t)(rowbase + r) * (T_STEPS * D) + k];
    }
    __syncthreads();

    // epilogue helpers (lambdas keep register context)
    auto tanh_store = [&](const float h4[4], int r0) {
#pragma unroll
        for (int r = 0; r < 4; r++)
            Hs[(r0 + r) * STRIDE + j] = tanh_acc(h4[r]);
    };
    auto update_store = [&](const float p4[4], int r0, int t) {
#pragma unroll
        for (int r = 0; r < 4; r++) {
            const int rr = r0 + r;
            float p_m = p4[r];
            float p_o = __shfl_xor_sync(0xffffffffu, p_m, 1);
            float y_m = Ys[rr * STRIDE + j];
            float y_o = __shfl_xor_sync(0xffffffffu, y_m, 1);
            float mu = even ? p_m : p_o;
            float om = even ? p_o : p_m;
            float y0 = even ? y_m : y_o;
            float y1 = even ? y_o : y_m;
            float e  = exp_small(DT * mu);
            float z  = DT * om, z2 = z * z;
            float c  = cos_small(z2);
            float s  = sin_small(z, z2);
            float n  = even ? e * (c * y0 - s * y1)
                            : e * (s * y0 - c * y1);   // reference: s*y0 - c*y1
            Ys[rr * STRIDE + j] = n;
            out[((size_t)(rowbase + rr) * T_STEPS + t) * D + j] = n;
        }
    };
#define BARG() asm volatile("bar.sync %0, 64;" :: "r"(bar) : "memory")

    float oA[4], oB[4];

    // prologue: G1(A, step 0)
    gemv4(w1p, Ys, rA, b1j, oA);
    tanh_store(oA, rA);
    BARG();

#pragma unroll 1
    for (int t = 0; t < T_STEPS - 1; t++) {
        // phase 2 of step t:  G2(A,t) || G1(B,t)
        dual_gemv4(w2p, Hs, rA, b2j, w1p, Ys, rB, b1j, oA, oB);
        update_store(oA, rA, t);     // writes Ys(A), out(A,t)
        tanh_store(oB, rB);          // writes Hs(B)
        BARG();
        // phase 1 of step t+1:  G1(A,t+1) || G2(B,t)
        dual_gemv4(w1p, Ys, rA, b1j, w2p, Hs, rB, b2j, oA, oB);
        tanh_store(oA, rA);          // writes Hs(A)
        update_store(oB, rB, t);     // writes Ys(B), out(B,t)
        BARG();
    }
    // tail: t = 255
    dual_gemv4(w2p, Hs, rA, b2j, w1p, Ys, rB, b1j, oA, oB);
    update_store(oA, rA, T_STEPS - 1);
    tanh_store(oB, rB);
    BARG();
    gemv4(w2p, Hs, rB, b2j, oB);
    update_store(oB, rB, T_STEPS - 1);
#undef BARG
}

extern "C" void kernel_launch(void* const* d_in, const int* in_sizes, int n_in,
                              void* d_out, int out_size) {
    const float* x  = (const float*)d_in[0];
    const float* W1 = (const float*)d_in[1];
    const float* b1 = (const float*)d_in[2];
    const float* W2 = (const float*)d_in[3];
    const float* b2 = (const float*)d_in[4];
    float* out = (float*)d_out;

    // 4096 rows / 32 per CTA = 128 CTAs; weights in registers, ~17KB static smem.
    koopman_kernel<<<NCTA, THREADS>>>(x, W1, b1, W2, b2, out);
}

// round 14
// speedup vs baseline: 1.3175x; 1.3131x over previous
#include <cuda_runtime.h>
#include <cstdint>

// KoopmanOperator: y_{t+1} = R(p(y_t)), 256 steps, y_0 = x[:,0,:]
//   h = tanh(y @ W1^T + b1);  p = h @ W2^T + b2
//   mu=p[2i], om=p[2i+1]; e=exp(dt*mu), c=cos(dt*om), s=sin(dt*om)
//   y'[2i] = e*(c*y0 - s*y1);  y'[2i+1] = e*(s*y0 - c*y1)   (per reference)
//
// Warp-specialized, 2 columns/thread (halves LDS instruction count — the
// measured structural wall). P1 warps 0-3: W1 cols (lane, lane+32) in regs,
// GEMV1+tanh -> Hs. P2 warps 4-7: W2 pair cols (2*lane, 2*lane+1) in regs,
// GEMV2 + in-register rotation update -> Ys, out. Pair (p, p+4) shares an
// SMSP, owns rows [8p, 8p+8) as blocks A/B, pipelined over named barriers:
//   PhaseA: G1(B,t) || G2(A,t);  PhaseB: G1(A,t+1) || G2(B,t).
// Inner loop: 4 broadcast LDS.128 -> 16 FFMA2 (ratio 4, was 2).

#define D 64
#define T_STEPS 256
#define ROWS_PER_CTA 32
#define THREADS 256
#define NCTA 128
#define STRIDE 68               // floats; 272B pitch
#define DT 0.01f

__device__ __forceinline__ void fma2(unsigned long long& d,
                                     unsigned long long a,
                                     unsigned long long b) {
    asm("fma.rn.f32x2 %0, %1, %2, %0;" : "+l"(d) : "l"(a), "l"(b));
}
__device__ __forceinline__ unsigned long long pack2(float x, float y) {
    unsigned long long u;
    asm("mov.b64 %0, {%1, %2};" : "=l"(u) : "f"(x), "f"(y));
    return u;
}
__device__ __forceinline__ float2 unpack2(unsigned long long u) {
    float2 f;
    asm("mov.b64 {%0, %1}, %2;" : "=f"(f.x), "=f"(f.y) : "l"(u));
    return f;
}

// Accurate fast tanh (~1e-6): EX2 + RCP.
__device__ __forceinline__ float tanh_acc(float x) {
    float ax = fabsf(x);
    float e  = __expf(-2.0f * ax);
    float t  = __fdividef(1.0f - e, 1.0f + e);
    return copysignf(t, x);
}
// Small-argument Taylor (|z| <~ 0.3): error < 1e-7, pure FFMA.
__device__ __forceinline__ float exp_small(float z) {
    float p = fmaf(z, 1.0f / 120.0f, 1.0f / 24.0f);
    p = fmaf(z, p, 1.0f / 6.0f);
    p = fmaf(z, p, 0.5f);
    p = fmaf(z, p, 1.0f);
    return fmaf(z, p, 1.0f);
}
__device__ __forceinline__ float cos_small(float z2) {
    float p = fmaf(z2, -1.0f / 720.0f, 1.0f / 24.0f);
    p = fmaf(z2, p, -0.5f);
    return fmaf(z2, p, 1.0f);
}
__device__ __forceinline__ float sin_small(float z, float z2) {
    float p = fmaf(z2, 1.0f / 120.0f, -1.0f / 6.0f);
    return z * fmaf(z2, p, 1.0f);
}

// 4 rows x 2 register-resident weight columns. Broadcast src loads.
// Per k-chunk: 4 LDS.128 feed 16 FFMA2.
__device__ __forceinline__ void gemv4x2(const unsigned long long (&wa)[32],
                                        const unsigned long long (&wb)[32],
                                        const float* __restrict__ src,
                                        int r0, float bA, float bB,
                                        float o[4][2]) {
    unsigned long long acc[4][2];
#pragma unroll
    for (int i = 0; i < 4; i++) {
        acc[i][0] = pack2(bA, 0.0f);
        acc[i][1] = pack2(bB, 0.0f);
    }
#pragma unroll
    for (int kc = 0; kc < D; kc += 4) {
        ulonglong2 v[4];
#pragma unroll
        for (int i = 0; i < 4; i++)
            v[i] = *reinterpret_cast<const ulonglong2*>(src + (r0 + i) * STRIDE + kc);
        const unsigned long long alo = wa[kc >> 1], ahi = wa[(kc >> 1) + 1];
        const unsigned long long blo = wb[kc >> 1], bhi = wb[(kc >> 1) + 1];
#pragma unroll
        for (int i = 0; i < 4; i++) {
            fma2(acc[i][0], alo, v[i].x);
            fma2(acc[i][1], blo, v[i].x);
        }
#pragma unroll
        for (int i = 0; i < 4; i++) {
            fma2(acc[i][0], ahi, v[i].y);
            fma2(acc[i][1], bhi, v[i].y);
        }
    }
#pragma unroll
    for (int i = 0; i < 4; i++) {
#pragma unroll
        for (int c = 0; c < 2; c++) {
            float2 f = unpack2(acc[i][c]);
            o[i][c] = f.x + f.y;
        }
    }
}

__global__ void __launch_bounds__(THREADS, 1)
koopman_kernel(const float* __restrict__ x,
               const float* __restrict__ W1g,
               const float* __restrict__ b1g,
               const float* __restrict__ W2g,
               const float* __restrict__ b2g,
               float* __restrict__ out) {
    __shared__ float Ys[ROWS_PER_CTA * STRIDE];
    __shared__ float Hs[ROWS_PER_CTA * STRIDE];

    const int tid  = threadIdx.x;
    const int w    = tid >> 5;
    const int lane = tid & 31;
    const bool isP1 = (w < 4);
    const int p    = isP1 ? w : (w - 4);     // pair 0..3; warps p and p+4 share SMSP p
    const int bar  = 1 + p;                  // named barrier per pair
    const int rA   = 8 * p;                  // block A rows [rA, rA+4)
    const int rB   = 8 * p + 4;              // block B rows [rB, rB+4)
    const int rowbase = blockIdx.x * ROWS_PER_CTA;

    // ---- y0 -> smem (all threads) ----
    for (int i = tid; i < ROWS_PER_CTA * D; i += THREADS) {
        int r = i >> 6, k = i & 63;
        Ys[r * STRIDE + k] = x[(size_t)(rowbase + r) * (T_STEPS * D) + k];
    }

#define BARP() asm volatile("bar.sync %0, 64;" :: "r"(bar) : "memory")

    if (isP1) {
        // ======== P1: GEMV1 + tanh producer ========
        const int cA = lane, cB = lane + 32;
        unsigned long long wa[32], wb[32];
#pragma unroll
        for (int kc = 0; kc < D; kc += 4) {
            float4 a = *reinterpret_cast<const float4*>(W1g + cA * D + kc);
            float4 b = *reinterpret_cast<const float4*>(W1g + cB * D + kc);
            wa[kc >> 1]       = pack2(a.x, a.y);
            wa[(kc >> 1) + 1] = pack2(a.z, a.w);
            wb[kc >> 1]       = pack2(b.x, b.y);
            wb[(kc >> 1) + 1] = pack2(b.z, b.w);
        }
        const float bA = b1g[cA], bB = b1g[cB];
        __syncthreads();                      // Ys init visible to all

        float o[4][2];
        // prologue: H(A, t=0)
        gemv4x2(wa, wb, Ys, rA, bA, bB, o);
#pragma unroll
        for (int i = 0; i < 4; i++) {
            Hs[(rA + i) * STRIDE + cA] = tanh_acc(o[i][0]);
            Hs[(rA + i) * STRIDE + cB] = tanh_acc(o[i][1]);
        }
        BARP();

#pragma unroll 1
        for (int t = 0; t < T_STEPS; t++) {
            // PhaseA: G1(B, t)
            gemv4x2(wa, wb, Ys, rB, bA, bB, o);
#pragma unroll
            for (int i = 0; i < 4; i++) {
                Hs[(rB + i) * STRIDE + cA] = tanh_acc(o[i][0]);
                Hs[(rB + i) * STRIDE + cB] = tanh_acc(o[i][1]);
            }
            BARP();
            // PhaseB: G1(A, t+1)  (skip on last step)
            if (t < T_STEPS - 1) {
                gemv4x2(wa, wb, Ys, rA, bA, bB, o);
#pragma unroll
                for (int i = 0; i < 4; i++) {
                    Hs[(rA + i) * STRIDE + cA] = tanh_acc(o[i][0]);
                    Hs[(rA + i) * STRIDE + cB] = tanh_acc(o[i][1]);
                }
            }
            BARP();
        }
    } else {
        // ======== P2: GEMV2 + rotation-update consumer ========
        const int j0 = 2 * lane, j1 = j0 + 1;
        unsigned long long wa[32], wb[32];
#pragma unroll
        for (int kc = 0; kc < D; kc += 4) {
            float4 a = *reinterpret_cast<const float4*>(W2g + j0 * D + kc);
            float4 b = *reinterpret_cast<const float4*>(W2g + j1 * D + kc);
            wa[kc >> 1]       = pack2(a.x, a.y);
            wa[(kc >> 1) + 1] = pack2(a.z, a.w);
            wb[kc >> 1]       = pack2(b.x, b.y);
            wb[(kc >> 1) + 1] = pack2(b.z, b.w);
        }
        const float bA = b2g[j0], bB = b2g[j1];
        __syncthreads();                      // Ys init visible to all

        float o[4][2];
        BARP();                               // matches P1 prologue barrier

        auto g2_update = [&](int r0, int t) {
            gemv4x2(wa, wb, Hs, r0, bA, bB, o);
#pragma unroll
            for (int i = 0; i < 4; i++) {
                const int r = r0 + i;
                float e  = exp_small(DT * o[i][0]);
                float z  = DT * o[i][1], z2 = z * z;
                float c  = cos_small(z2);
                float s  = sin_small(z, z2);
                float2 y = *reinterpret_cast<const float2*>(Ys + r * STRIDE + j0);
                float n0 = e * (c * y.x - s * y.y);
                float n1 = e * (s * y.x - c * y.y);   // reference: s*y0 - c*y1
                *reinterpret_cast<float2*>(Ys + r * STRIDE + j0) = make_float2(n0, n1);
                const size_t ob = ((size_t)(rowbase + r) * T_STEPS + t) * D + j0;
                *reinterpret_cast<float2*>(out + ob) = make_float2(n0, n1);
            }
        };

#pragma unroll 1
        for (int t = 0; t < T_STEPS; t++) {
            // PhaseA: G2(A, t)  (Hs(A) written by P1 in previous phase)
            g2_update(rA, t);
            BARP();
            // PhaseB: G2(B, t)  (Hs(B) written by P1 in PhaseA)
            g2_update(rB, t);
            BARP();
        }
    }
#undef BARP
}

extern "C" void kernel_launch(void* const* d_in, const int* in_sizes, int n_in,
                              void* d_out, int out_size) {
    const float* x  = (const float*)d_in[0];
    const float* W1 = (const float*)d_in[1];
    const float* b1 = (const float*)d_in[2];
    const float* W2 = (const float*)d_in[3];
    const float* b2 = (const float*)d_in[4];
    float* out = (float*)d_out;

    // 4096 rows / 32 per CTA = 128 CTAs; weights in registers; ~17 KB smem.
    koopman_kernel<<<NCTA, THREADS>>>(x, W1, b1, W2, b2, out);
}